// round 5
// baseline (speedup 1.0000x reference)
#include <cuda_runtime.h>

// Problem-fixed shapes (setup_inputs): R=4000, C=20, K=3, H=W=1024, h=w=128.
#define HH 1024
#define WW 1024
#define CC 20
#define hh 128
#define ww 128
#define C1 21      // refine_result last dim = C+1
#define EPSF 1e-6f
#define NSEG 32
#define SEGH 32                 // rows per segment
#define MAXB 16384              // events per (c,seg) bucket; hard max = 4*R = 16000
#define GCOL 8                  // columns per thread in k_B (128 thr * 8 = 1024)

// Static scratch (no runtime allocation).
// Event: .x = x | (y_local<<10), .y = float bits of +-s.
__device__ int2  g_ev [CC][NSEG][MAXB];     // unsorted events
__device__ int2  g_evs[CC][NSEG][MAXB];     // row-sorted events
__device__ int   g_cnt[CC][NSEG];           // bucket sizes
__device__ float g_seg[CC][NSEG][WW];       // per-segment column-sum PREFIX over x
__device__ float g_Rm[CC][hh][ww];          // sampled integral-image values
__device__ int   g_minb[CC];                // per-channel min of M (float bits)
__device__ int   g_maxb[CC];                // per-channel max of M (float bits)

__device__ __forceinline__ void atomicMinF(int* addr, float v) {
    int old = *addr;
    while (__int_as_float(old) > v) {
        int assumed = old;
        old = atomicCAS(addr, assumed, __float_as_int(v));
        if (old == assumed) break;
    }
}
__device__ __forceinline__ void atomicMaxF(int* addr, float v) {
    int old = *addr;
    while (__int_as_float(old) < v) {
        int assumed = old;
        old = atomicCAS(addr, assumed, __float_as_int(v));
        if (old == assumed) break;
    }
}

// ---------------------------------------------------------------------------
// 0) Reset counters + min/max + output scalar. One block.
__global__ void k_zero(float* __restrict__ out) {
    int t = threadIdx.x;
    if (t == 0) out[0] = 0.f;
    if (t < CC * NSEG) ((int*)g_cnt)[t] = 0;
    if (t < CC) {
        g_minb[t] = __float_as_int(3.4e38f);
        g_maxb[t] = __float_as_int(-3.4e38f);
    }
}

// ---------------------------------------------------------------------------
// 1) Scores + sparse event emission. grid (R/256, CC); invalid channels exit.
__device__ __forceinline__ void emit_row(int c, int y, int x1, float s1, int x2, float s2) {
    if (y >= HH) return;                   // reference clips row H away via M[:H]
    int seg = y >> 5, yl = y & 31;
    int2 e1 = make_int2(x1 | (yl << 10), __float_as_int(s1));
    if (x2 < WW) {
        int idx = atomicAdd(&g_cnt[c][seg], 2);
        g_ev[c][seg][idx]     = e1;
        g_ev[c][seg][idx + 1] = make_int2(x2 | (yl << 10), __float_as_int(s2));
    } else {
        int idx = atomicAdd(&g_cnt[c][seg], 1);
        g_ev[c][seg][idx] = e1;
    }
}

__global__ void k_scatter(const float* __restrict__ refine,
                          const float* __restrict__ rois,
                          const int*   __restrict__ labels,
                          int R) {
    int c = blockIdx.y;
    if (labels[c] != 1) return;            // scores *= vmf
    int r = blockIdx.x * blockDim.x + threadIdx.x;
    if (r >= R) return;
    int base = r * C1 + c + 1;             // avg[:,1:]
    float s = (refine[base] + refine[R * C1 + base] + refine[2 * R * C1 + base]) * (1.0f / 3.0f);
    if (s < 0.3f) return;                  // SCORE_THRES
    int x1 = (int)rois[r * 5 + 1];
    int y1 = (int)rois[r * 5 + 2];
    int x2 = (int)rois[r * 5 + 3];
    int y2 = (int)rois[r * 5 + 4];
    // M(y,x) = sum s * [y1<=y<y2] * [x1<=x<x2]
    emit_row(c, y1, x1,  s, x2, -s);
    emit_row(c, y2, x1, -s, x2,  s);
}

// ---------------------------------------------------------------------------
// 2) Per bucket: (a) column-sum prefix g_seg; (b) counting-sort events by
//    local row into g_evs. grid (NSEG, CC), 1024 thr.
__global__ __launch_bounds__(1024) void k_A(const int* __restrict__ labels) {
    int c = blockIdx.y;
    if (labels[c] != 1) return;
    int seg = blockIdx.x, t = threadIdx.x;

    __shared__ float arr[WW];
    __shared__ int   cnt[SEGH + 1];
    __shared__ int   cur[SEGH];

    arr[t] = 0.f;
    if (t <= SEGH) cnt[t] = 0;
    __syncthreads();

    int E = g_cnt[c][seg];
    for (int i = t; i < E; i += 1024) {
        int2 e = g_ev[c][seg][i];
        atomicAdd(&arr[e.x & 0x3FF], __int_as_float(e.y));
        atomicAdd(&cnt[(e.x >> 10) + 1], 1);
    }
    __syncthreads();

    if (t == 0) {
        int acc = 0;
        #pragma unroll
        for (int j = 0; j <= SEGH; ++j) { acc += cnt[j]; cnt[j] = acc; }
        #pragma unroll
        for (int j = 0; j < SEGH; ++j) cur[j] = cnt[j];
    }
    __syncthreads();

    // Place events in row-sorted order (global; within-row order irrelevant).
    for (int i = t; i < E; i += 1024) {
        int2 e = g_ev[c][seg][i];
        int p = atomicAdd(&cur[e.x >> 10], 1);
        g_evs[c][seg][p] = e;
    }

    // Hillis-Steele inclusive scan of the 1024 column weights.
    #pragma unroll
    for (int off = 1; off < 1024; off <<= 1) {
        float v = (t >= off) ? arr[t - off] : 0.f;
        __syncthreads();
        arr[t] += v;
        __syncthreads();
    }
    g_seg[c][seg][t] = arr[t];
}

// ---------------------------------------------------------------------------
// 3) Fused column scan from sorted sparse events. 128 threads per bucket,
//    each thread owns 8 contiguous columns [8t, 8t+8):
//      run(8t+g) = common + ofs[g]
//    Event at xe: threads right of owner do common += se (1 op / 8 cols);
//    owner thread updates ofs[g>=xe&7]. Rows between events share state ->
//    one min/max update per gap + <=4 sampled-row writes.
//    grid (NSEG, CC), 128 thr.
__global__ __launch_bounds__(128) void k_B(const int* __restrict__ labels) {
    int c = blockIdx.y;
    if (labels[c] != 1) return;
    int seg = blockIdx.x, t = threadIdx.x;

    // Per-column state.
    float ofs[GCOL];
    #pragma unroll
    for (int g = 0; g < GCOL; ++g) ofs[g] = 0.f;

    // Base: integral of all segments above this one at each owned column.
    for (int s = 0; s < seg; ++s) {
        #pragma unroll
        for (int g = 0; g < GCOL; ++g)
            ofs[g] += g_seg[c][s][t * GCOL + g];
    }

    float common = 0.f;
    float min_ofs = 0.f, max_ofs = 0.f;
    bool dirty = true;
    float mn = 3.4e38f, mx = -3.4e38f;
    int y = 0;

    int E = g_cnt[c][seg];
    const int2* evp = &g_evs[c][seg][0];

    for (int i = 0; i <= E; ++i) {
        int ey, xe; float se;
        if (i < E) {
            int2 e = evp[i];                 // uniform addr: L1 broadcast
            ey = e.x >> 10;
            xe = e.x & 0x3FF;
            se = __int_as_float(e.y);
        } else {
            ey = SEGH; xe = 0; se = 0.f;     // sentinel: flush remaining rows
        }

        if (ey > y) {                        // warp-uniform gap advance
            if (dirty) {
                float a0 = fminf(ofs[0], ofs[1]), a1 = fminf(ofs[2], ofs[3]);
                float a2 = fminf(ofs[4], ofs[5]), a3 = fminf(ofs[6], ofs[7]);
                min_ofs = fminf(fminf(a0, a1), fminf(a2, a3));
                float b0 = fmaxf(ofs[0], ofs[1]), b1 = fmaxf(ofs[2], ofs[3]);
                float b2 = fmaxf(ofs[4], ofs[5]), b3 = fmaxf(ofs[6], ofs[7]);
                max_ofs = fmaxf(fmaxf(b0, b1), fmaxf(b2, b3));
                dirty = false;
            }
            mn = fminf(mn, common + min_ofs);
            mx = fmaxf(mx, common + max_ofs);
            // Sampled rows (y%8==0) in [y, ey): all share the same state.
            int ys = (y + 7) & ~7;
            if (ys < ey) {
                float sval = common + ofs[0];          // column 8t
                for (; ys < ey; ys += 8)
                    g_Rm[c][seg * 4 + (ys >> 3)][t] = sval;
            }
            y = ey;
        }

        if (i < E) {
            int owner = xe >> 3;
            if (t > owner) {
                common += se;
            } else if (t == owner) {
                int g0 = xe & 7;
                #pragma unroll
                for (int g = 0; g < GCOL; ++g)
                    if (g >= g0) ofs[g] += se;
                dirty = true;
            }
        }
    }

    // Block-wide min/max reduce + channel atomics.
    __shared__ float rmn[128], rmx[128];
    rmn[t] = mn; rmx[t] = mx;
    __syncthreads();
    for (int o = 64; o; o >>= 1) {
        if (t < o) {
            rmn[t] = fminf(rmn[t], rmn[t + o]);
            rmx[t] = fmaxf(rmx[t], rmx[t + o]);
        }
        __syncthreads();
    }
    if (t == 0) {
        atomicMinF(&g_minb[c], rmn[0]);
        atomicMaxF(&g_maxb[c], rmx[0]);
    }
}

// ---------------------------------------------------------------------------
// 4) Per-channel loss, normalized and atomically accumulated into out[0].
//    grid (CC), 128 thr.
__global__ void k_loss(const float* __restrict__ blob,
                       const int*   __restrict__ labels,
                       float* __restrict__ out) {
    int c = blockIdx.x, t = threadIdx.x;
    bool valid = (labels[c] == 1);
    const float* B = blob + c * hh * ww;

    float cmax = 0.f;
    for (int i = 0; i < hh; ++i) cmax = fmaxf(cmax, B[i * ww + t]);
    float rmax = 0.f;
    for (int j = 0; j < ww; ++j) rmax = fmaxf(rmax, B[t * ww + j]);
    cmax = fminf(fmaxf(cmax, EPSF), 1.f - EPSF);
    rmax = fminf(fmaxf(rmax, EPSF), 1.f - EPSF);

    float vx, vy;
    if (valid) {
        float mnv = __int_as_float(g_minb[c]);
        float mxv = __int_as_float(g_maxb[c]);
        float thr = mnv + 0.5f * (mxv - mnv + EPSF);   // normalized >= 0.5
        float scol = -3.4e38f, srow = -3.4e38f;
        for (int i = 0; i < hh; ++i) scol = fmaxf(scol, g_Rm[c][i][t]);
        for (int j = 0; j < ww; ++j) srow = fmaxf(srow, g_Rm[c][t][j]);
        vx = (scol >= thr) ? -logf(cmax) : 0.f;
        vy = (srow >= thr) ? -logf(rmax) : 0.f;
    } else {
        vx = -logf(1.f - cmax);
        vy = -logf(1.f - rmax);
    }

    __shared__ float sx[128], sy[128];
    sx[t] = vx; sy[t] = vy;
    __syncthreads();
    for (int o = 64; o; o >>= 1) {
        if (t < o) { sx[t] += sx[t + o]; sy[t] += sy[t + o]; }
        __syncthreads();
    }
    if (t == 0) {
        float vc = 0.f;
        for (int k = 0; k < CC; ++k) vc += (labels[k] == 1) ? 1.f : 0.f;
        float nvc = (float)CC - vc;
        float denom = valid ? vc : nvc;
        atomicAdd(out, sx[0] / (denom * (float)ww) + sy[0] / (denom * (float)hh));
    }
}

// ---------------------------------------------------------------------------
extern "C" void kernel_launch(void* const* d_in, const int* in_sizes, int n_in,
                              void* d_out, int out_size) {
    // metadata order: mil_result(unused), refine_result, blob_conv, rois, labels, H, W
    const float* refine = (const float*)d_in[1];
    const float* blob   = (const float*)d_in[2];
    const float* rois   = (const float*)d_in[3];
    const int*   labels = (const int*)  d_in[4];
    int R = in_sizes[3] / 5;
    float* out = (float*)d_out;

    k_zero   <<<1, 1024>>>(out);
    k_scatter<<<dim3((R + 255) / 256, CC), 256>>>(refine, rois, labels, R);
    k_A      <<<dim3(NSEG, CC), 1024>>>(labels);
    k_B      <<<dim3(NSEG, CC), 128>>>(labels);
    k_loss   <<<CC, 128>>>(blob, labels, out);
}

// round 6
// speedup vs baseline: 1.4948x; 1.4948x over previous
#include <cuda_runtime.h>

// Problem-fixed shapes (setup_inputs): R=4000, C=20, K=3, H=W=1024, h=w=128.
#define HH 1024
#define WW 1024
#define CC 20
#define hh 128
#define ww 128
#define C1 21      // refine_result last dim = C+1
#define EPSF 1e-6f
#define NSEG 64
#define SEGH 16                 // rows per segment
#define MAXB 16384              // events per (c,seg) bucket; hard max = 4*R = 16000
#define GCOL 8                  // columns per thread in k_B (128 thr * 8 = 1024)
#define EB   8                  // k_B event prefetch depth

// Static scratch (no runtime allocation).
// Event: .x = x | (y_local<<10)  (y_local < 16), .y = float bits of +-s.
__device__ int2  g_ev [CC][NSEG][MAXB];     // unsorted events
__device__ int2  g_evs[CC][NSEG][MAXB];     // row-sorted events
__device__ int   g_cnt[CC][NSEG];           // bucket sizes
__device__ float g_seg[CC][NSEG][WW];       // per-segment column-sum PREFIX over x
__device__ float g_pre[CC][NSEG][WW];       // vertical prefix of g_seg (exclusive)
__device__ float g_Rm[CC][hh][ww];          // sampled integral-image values
__device__ int   g_minb[CC];                // per-channel min of M (float bits)
__device__ int   g_maxb[CC];                // per-channel max of M (float bits)

__device__ __forceinline__ void atomicMinF(int* addr, float v) {
    int old = *addr;
    while (__int_as_float(old) > v) {
        int assumed = old;
        old = atomicCAS(addr, assumed, __float_as_int(v));
        if (old == assumed) break;
    }
}
__device__ __forceinline__ void atomicMaxF(int* addr, float v) {
    int old = *addr;
    while (__int_as_float(old) < v) {
        int assumed = old;
        old = atomicCAS(addr, assumed, __float_as_int(v));
        if (old == assumed) break;
    }
}

// ---------------------------------------------------------------------------
// 0) Reset counters + min/max + output scalar. One block.
__global__ void k_zero(float* __restrict__ out) {
    int t = threadIdx.x;
    if (t == 0) out[0] = 0.f;
    for (int i = t; i < CC * NSEG; i += 1024) ((int*)g_cnt)[i] = 0;
    if (t < CC) {
        g_minb[t] = __float_as_int(3.4e38f);
        g_maxb[t] = __float_as_int(-3.4e38f);
    }
}

// ---------------------------------------------------------------------------
// 1) Scores + sparse event emission. grid (R/256, CC); invalid channels exit.
__device__ __forceinline__ void emit_row(int c, int y, int x1, float s1, int x2, float s2) {
    if (y >= HH) return;                   // reference clips row H away via M[:H]
    int seg = y >> 4, yl = y & (SEGH - 1);
    int2 e1 = make_int2(x1 | (yl << 10), __float_as_int(s1));
    if (x2 < WW) {
        int idx = atomicAdd(&g_cnt[c][seg], 2);
        g_ev[c][seg][idx]     = e1;
        g_ev[c][seg][idx + 1] = make_int2(x2 | (yl << 10), __float_as_int(s2));
    } else {
        int idx = atomicAdd(&g_cnt[c][seg], 1);
        g_ev[c][seg][idx] = e1;
    }
}

__global__ void k_scatter(const float* __restrict__ refine,
                          const float* __restrict__ rois,
                          const int*   __restrict__ labels,
                          int R) {
    int c = blockIdx.y;
    if (labels[c] != 1) return;            // scores *= vmf
    int r = blockIdx.x * blockDim.x + threadIdx.x;
    if (r >= R) return;
    int base = r * C1 + c + 1;             // avg[:,1:]
    float s = (refine[base] + refine[R * C1 + base] + refine[2 * R * C1 + base]) * (1.0f / 3.0f);
    if (s < 0.3f) return;                  // SCORE_THRES
    int x1 = (int)rois[r * 5 + 1];
    int y1 = (int)rois[r * 5 + 2];
    int x2 = (int)rois[r * 5 + 3];
    int y2 = (int)rois[r * 5 + 4];
    // M(y,x) = sum s * [y1<=y<y2] * [x1<=x<x2]
    emit_row(c, y1, x1,  s, x2, -s);
    emit_row(c, y2, x1, -s, x2,  s);
}

// ---------------------------------------------------------------------------
// 2) Per bucket: (a) column-sum prefix g_seg (shfl-based scan);
//    (b) counting-sort events by local row into g_evs. grid (NSEG, CC), 1024 thr.
__global__ __launch_bounds__(1024) void k_A(const int* __restrict__ labels) {
    int c = blockIdx.y;
    if (labels[c] != 1) return;
    int seg = blockIdx.x, t = threadIdx.x;
    int lane = t & 31, warp = t >> 5;

    __shared__ float arr[WW];
    __shared__ float wsum[32];
    __shared__ int   cnt[SEGH + 1];
    __shared__ int   cur[SEGH];

    arr[t] = 0.f;
    if (t <= SEGH) cnt[t] = 0;
    __syncthreads();

    int E = g_cnt[c][seg];
    for (int i = t; i < E; i += 1024) {
        int2 e = g_ev[c][seg][i];
        atomicAdd(&arr[e.x & 0x3FF], __int_as_float(e.y));
        atomicAdd(&cnt[(e.x >> 10) + 1], 1);
    }
    __syncthreads();

    if (t == 0) {
        int acc = 0;
        #pragma unroll
        for (int j = 0; j <= SEGH; ++j) { acc += cnt[j]; cnt[j] = acc; }
        #pragma unroll
        for (int j = 0; j < SEGH; ++j) cur[j] = cnt[j];
    }
    // Start the scan: warp-level inclusive scan of arr[t].
    float v = arr[t];
    #pragma unroll
    for (int o = 1; o < 32; o <<= 1) {
        float n = __shfl_up_sync(0xFFFFFFFF, v, o);
        if (lane >= o) v += n;
    }
    if (lane == 31) wsum[warp] = v;
    __syncthreads();
    if (warp == 0) {
        float w = wsum[lane];
        #pragma unroll
        for (int o = 1; o < 32; o <<= 1) {
            float n = __shfl_up_sync(0xFFFFFFFF, w, o);
            if (lane >= o) w += n;
        }
        wsum[lane] = w;
    }
    __syncthreads();
    if (warp > 0) v += wsum[warp - 1];
    g_seg[c][seg][t] = v;

    // Place events in row-sorted order (within-row order irrelevant).
    for (int i = t; i < E; i += 1024) {
        int2 e = g_ev[c][seg][i];
        int p = atomicAdd(&cur[e.x >> 10], 1);
        g_evs[c][seg][p] = e;
    }
}

// ---------------------------------------------------------------------------
// 2.5) Vertical (segment-axis) exclusive prefix of g_seg -> g_pre.
//      grid (CC), 1024 thr; thread = column x.
__global__ __launch_bounds__(1024) void k_P(const int* __restrict__ labels) {
    int c = blockIdx.x;
    if (labels[c] != 1) return;
    int x = threadIdx.x;
    float run = 0.f;
    #pragma unroll 8
    for (int s = 0; s < NSEG; ++s) {
        g_pre[c][s][x] = run;
        run += g_seg[c][s][x];
    }
}

// ---------------------------------------------------------------------------
// 3) Fused column scan from sorted sparse events. 128 threads per bucket,
//    thread owns 8 contiguous columns: run(8t+g) = common + ofs[g].
//    Events prefetched 8-deep into registers (uniform-address L1 broadcast,
//    MLP=8) to hide load latency. grid (NSEG, CC), 128 thr.
__global__ __launch_bounds__(128) void k_B(const int* __restrict__ labels) {
    int c = blockIdx.y;
    if (labels[c] != 1) return;
    int seg = blockIdx.x, t = threadIdx.x;

    float ofs[GCOL];
    #pragma unroll
    for (int g = 0; g < GCOL; ++g) ofs[g] = g_pre[c][seg][t * GCOL + g];

    float common = 0.f;
    float min_ofs = 0.f, max_ofs = 0.f;
    bool dirty = true;
    float mn = 3.4e38f, mx = -3.4e38f;
    int y = 0;

    int E = g_cnt[c][seg];
    const int2* evp = &g_evs[c][seg][0];

    int i = 0;
    while (i < E) {
        int m = min(EB, E - i);
        int2 eb[EB];
        #pragma unroll
        for (int j = 0; j < EB; ++j)
            if (j < m) eb[j] = evp[i + j];          // independent loads, MLP=EB
        #pragma unroll
        for (int j = 0; j < EB; ++j) {
            if (j >= m) break;
            int2 e = eb[j];
            int ey = e.x >> 10;
            int xe = e.x & 0x3FF;
            float se = __int_as_float(e.y);

            if (ey > y) {                            // warp-uniform gap advance
                if (dirty) {
                    float a0 = fminf(ofs[0], ofs[1]), a1 = fminf(ofs[2], ofs[3]);
                    float a2 = fminf(ofs[4], ofs[5]), a3 = fminf(ofs[6], ofs[7]);
                    min_ofs = fminf(fminf(a0, a1), fminf(a2, a3));
                    float b0 = fmaxf(ofs[0], ofs[1]), b1 = fmaxf(ofs[2], ofs[3]);
                    float b2 = fmaxf(ofs[4], ofs[5]), b3 = fmaxf(ofs[6], ofs[7]);
                    max_ofs = fmaxf(fmaxf(b0, b1), fmaxf(b2, b3));
                    dirty = false;
                }
                mn = fminf(mn, common + min_ofs);
                mx = fmaxf(mx, common + max_ofs);
                int ys = (y + 7) & ~7;               // sampled local rows (0 or 8)
                if (ys < ey) {
                    float sval = common + ofs[0];    // column 8t
                    for (; ys < ey; ys += 8)
                        g_Rm[c][seg * (SEGH / 8) + (ys >> 3)][t] = sval;
                }
                y = ey;
            }

            int owner = xe >> 3;
            if (t > owner) {
                common += se;
            } else if (t == owner) {
                int g0 = xe & 7;
                #pragma unroll
                for (int g = 0; g < GCOL; ++g)
                    if (g >= g0) ofs[g] += se;
                dirty = true;
            }
        }
        i += m;
    }

    // Flush remaining rows [y, SEGH).
    {
        if (dirty) {
            float a0 = fminf(ofs[0], ofs[1]), a1 = fminf(ofs[2], ofs[3]);
            float a2 = fminf(ofs[4], ofs[5]), a3 = fminf(ofs[6], ofs[7]);
            min_ofs = fminf(fminf(a0, a1), fminf(a2, a3));
            float b0 = fmaxf(ofs[0], ofs[1]), b1 = fmaxf(ofs[2], ofs[3]);
            float b2 = fmaxf(ofs[4], ofs[5]), b3 = fmaxf(ofs[6], ofs[7]);
            max_ofs = fmaxf(fmaxf(b0, b1), fmaxf(b2, b3));
        }
        if (y < SEGH) {
            mn = fminf(mn, common + min_ofs);
            mx = fmaxf(mx, common + max_ofs);
            int ys = (y + 7) & ~7;
            float sval = common + ofs[0];
            for (; ys < SEGH; ys += 8)
                g_Rm[c][seg * (SEGH / 8) + (ys >> 3)][t] = sval;
        }
    }

    // Block-wide min/max reduce: warp shfl + cross-warp smem.
    int lane = t & 31, warp = t >> 5;
    #pragma unroll
    for (int o = 16; o; o >>= 1) {
        mn = fminf(mn, __shfl_xor_sync(0xFFFFFFFF, mn, o));
        mx = fmaxf(mx, __shfl_xor_sync(0xFFFFFFFF, mx, o));
    }
    __shared__ float rmn[4], rmx[4];
    if (lane == 0) { rmn[warp] = mn; rmx[warp] = mx; }
    __syncthreads();
    if (t == 0) {
        float fmn = fminf(fminf(rmn[0], rmn[1]), fminf(rmn[2], rmn[3]));
        float fmx = fmaxf(fmaxf(rmx[0], rmx[1]), fmaxf(rmx[2], rmx[3]));
        atomicMinF(&g_minb[c], fmn);
        atomicMaxF(&g_maxb[c], fmx);
    }
}

// ---------------------------------------------------------------------------
// 4) Per-channel loss, normalized and atomically accumulated into out[0].
//    grid (CC), 128 thr.
__global__ void k_loss(const float* __restrict__ blob,
                       const int*   __restrict__ labels,
                       float* __restrict__ out) {
    int c = blockIdx.x, t = threadIdx.x;
    bool valid = (labels[c] == 1);
    const float* B = blob + c * hh * ww;

    float cmax = 0.f;
    for (int i = 0; i < hh; ++i) cmax = fmaxf(cmax, B[i * ww + t]);
    float rmax = 0.f;
    for (int j = 0; j < ww; ++j) rmax = fmaxf(rmax, B[t * ww + j]);
    cmax = fminf(fmaxf(cmax, EPSF), 1.f - EPSF);
    rmax = fminf(fmaxf(rmax, EPSF), 1.f - EPSF);

    float vx, vy;
    if (valid) {
        float mnv = __int_as_float(g_minb[c]);
        float mxv = __int_as_float(g_maxb[c]);
        float thr = mnv + 0.5f * (mxv - mnv + EPSF);   // normalized >= 0.5
        float scol = -3.4e38f, srow = -3.4e38f;
        for (int i = 0; i < hh; ++i) scol = fmaxf(scol, g_Rm[c][i][t]);
        for (int j = 0; j < ww; ++j) srow = fmaxf(srow, g_Rm[c][t][j]);
        vx = (scol >= thr) ? -logf(cmax) : 0.f;
        vy = (srow >= thr) ? -logf(rmax) : 0.f;
    } else {
        vx = -logf(1.f - cmax);
        vy = -logf(1.f - rmax);
    }

    __shared__ float sx[128], sy[128];
    sx[t] = vx; sy[t] = vy;
    __syncthreads();
    for (int o = 64; o; o >>= 1) {
        if (t < o) { sx[t] += sx[t + o]; sy[t] += sy[t + o]; }
        __syncthreads();
    }
    if (t == 0) {
        float vc = 0.f;
        for (int k = 0; k < CC; ++k) vc += (labels[k] == 1) ? 1.f : 0.f;
        float nvc = (float)CC - vc;
        float denom = valid ? vc : nvc;
        atomicAdd(out, sx[0] / (denom * (float)ww) + sy[0] / (denom * (float)hh));
    }
}

// ---------------------------------------------------------------------------
extern "C" void kernel_launch(void* const* d_in, const int* in_sizes, int n_in,
                              void* d_out, int out_size) {
    // metadata order: mil_result(unused), refine_result, blob_conv, rois, labels, H, W
    const float* refine = (const float*)d_in[1];
    const float* blob   = (const float*)d_in[2];
    const float* rois   = (const float*)d_in[3];
    const int*   labels = (const int*)  d_in[4];
    int R = in_sizes[3] / 5;
    float* out = (float*)d_out;

    k_zero   <<<1, 1024>>>(out);
    k_scatter<<<dim3((R + 255) / 256, CC), 256>>>(refine, rois, labels, R);
    k_A      <<<dim3(NSEG, CC), 1024>>>(labels);
    k_P      <<<CC, 1024>>>(labels);
    k_B      <<<dim3(NSEG, CC), 128>>>(labels);
    k_loss   <<<CC, 128>>>(blob, labels, out);
}

// round 7
// speedup vs baseline: 1.7726x; 1.1859x over previous
#include <cuda_runtime.h>

// Problem-fixed shapes (setup_inputs): R=4000, C=20, K=3, H=W=1024, h=w=128.
#define HH 1024
#define WW 1024
#define CC 20
#define hh 128
#define ww 128
#define C1 21      // refine_result last dim = C+1
#define EPSF 1e-6f
#define NSEG 64
#define SEGH 16                 // rows per segment
#define MAXB 16384              // events per (c,seg) bucket; hard max = 4*R = 16000
#define GCOL 8                  // columns per thread in k_B (128 thr * 8 = 1024)
#define EB   8                  // k_B event prefetch depth

// Static scratch (no runtime allocation).
// Event: .x = x | (y_local<<10)  (y_local < 16), .y = float bits of +-s.
__device__ int2  g_ev [CC][NSEG][MAXB];     // unsorted events
__device__ int2  g_evs[CC][NSEG][MAXB];     // row-sorted events
__device__ int   g_cnt[CC][NSEG];           // bucket sizes
__device__ float g_seg[CC][NSEG][WW];       // per-segment column-sum PREFIX over x
__device__ float g_Rm[CC][hh][ww];          // sampled integral-image values
__device__ int   g_minb[CC];                // per-channel min of M (float bits)
__device__ int   g_maxb[CC];                // per-channel max of M (float bits)

__device__ __forceinline__ void atomicMinF(int* addr, float v) {
    int old = *addr;
    while (__int_as_float(old) > v) {
        int assumed = old;
        old = atomicCAS(addr, assumed, __float_as_int(v));
        if (old == assumed) break;
    }
}
__device__ __forceinline__ void atomicMaxF(int* addr, float v) {
    int old = *addr;
    while (__int_as_float(old) < v) {
        int assumed = old;
        old = atomicCAS(addr, assumed, __float_as_int(v));
        if (old == assumed) break;
    }
}

// ---------------------------------------------------------------------------
// 0) Reset counters + min/max + output scalar. One block.
__global__ void k_zero(float* __restrict__ out) {
    int t = threadIdx.x;
    if (t == 0) out[0] = 0.f;
    for (int i = t; i < CC * NSEG; i += 1024) ((int*)g_cnt)[i] = 0;
    if (t < CC) {
        g_minb[t] = __float_as_int(3.4e38f);
        g_maxb[t] = __float_as_int(-3.4e38f);
    }
}

// ---------------------------------------------------------------------------
// 1) Scores + sparse event emission. grid (R/256, CC); invalid channels exit.
__device__ __forceinline__ void emit_row(int c, int y, int x1, float s1, int x2, float s2) {
    if (y >= HH) return;                   // reference clips row H away via M[:H]
    int seg = y >> 4, yl = y & (SEGH - 1);
    int2 e1 = make_int2(x1 | (yl << 10), __float_as_int(s1));
    if (x2 < WW) {
        int idx = atomicAdd(&g_cnt[c][seg], 2);
        g_ev[c][seg][idx]     = e1;
        g_ev[c][seg][idx + 1] = make_int2(x2 | (yl << 10), __float_as_int(s2));
    } else {
        int idx = atomicAdd(&g_cnt[c][seg], 1);
        g_ev[c][seg][idx] = e1;
    }
}

__global__ void k_scatter(const float* __restrict__ refine,
                          const float* __restrict__ rois,
                          const int*   __restrict__ labels,
                          int R) {
    int c = blockIdx.y;
    if (labels[c] != 1) return;            // scores *= vmf
    int r = blockIdx.x * blockDim.x + threadIdx.x;
    if (r >= R) return;
    int base = r * C1 + c + 1;             // avg[:,1:]
    float s = (refine[base] + refine[R * C1 + base] + refine[2 * R * C1 + base]) * (1.0f / 3.0f);
    if (s < 0.3f) return;                  // SCORE_THRES
    int x1 = (int)rois[r * 5 + 1];
    int y1 = (int)rois[r * 5 + 2];
    int x2 = (int)rois[r * 5 + 3];
    int y2 = (int)rois[r * 5 + 4];
    // M(y,x) = sum s * [y1<=y<y2] * [x1<=x<x2]
    emit_row(c, y1, x1,  s, x2, -s);
    emit_row(c, y2, x1, -s, x2,  s);
}

// ---------------------------------------------------------------------------
// 2) Per bucket: (a) column-sum prefix g_seg (shfl-based scan);
//    (b) counting-sort events by local row into g_evs. grid (NSEG, CC), 1024 thr.
__global__ __launch_bounds__(1024) void k_A(const int* __restrict__ labels) {
    int c = blockIdx.y;
    if (labels[c] != 1) return;
    int seg = blockIdx.x, t = threadIdx.x;
    int lane = t & 31, warp = t >> 5;

    __shared__ float arr[WW];
    __shared__ float wsum[32];
    __shared__ int   cnt[SEGH + 1];
    __shared__ int   cur[SEGH];

    arr[t] = 0.f;
    if (t <= SEGH) cnt[t] = 0;
    __syncthreads();

    int E = g_cnt[c][seg];
    for (int i = t; i < E; i += 1024) {
        int2 e = g_ev[c][seg][i];
        atomicAdd(&arr[e.x & 0x3FF], __int_as_float(e.y));
        atomicAdd(&cnt[(e.x >> 10) + 1], 1);
    }
    __syncthreads();

    if (t == 0) {
        int acc = 0;
        #pragma unroll
        for (int j = 0; j <= SEGH; ++j) { acc += cnt[j]; cnt[j] = acc; }
        #pragma unroll
        for (int j = 0; j < SEGH; ++j) cur[j] = cnt[j];
    }
    // Warp-level inclusive scan of arr[t] (1024 columns).
    float v = arr[t];
    #pragma unroll
    for (int o = 1; o < 32; o <<= 1) {
        float n = __shfl_up_sync(0xFFFFFFFF, v, o);
        if (lane >= o) v += n;
    }
    if (lane == 31) wsum[warp] = v;
    __syncthreads();
    if (warp == 0) {
        float w = wsum[lane];
        #pragma unroll
        for (int o = 1; o < 32; o <<= 1) {
            float n = __shfl_up_sync(0xFFFFFFFF, w, o);
            if (lane >= o) w += n;
        }
        wsum[lane] = w;
    }
    __syncthreads();
    if (warp > 0) v += wsum[warp - 1];
    g_seg[c][seg][t] = v;

    // Place events in row-sorted order (within-row order irrelevant).
    for (int i = t; i < E; i += 1024) {
        int2 e = g_ev[c][seg][i];
        int p = atomicAdd(&cur[e.x >> 10], 1);
        g_evs[c][seg][p] = e;
    }
}

// ---------------------------------------------------------------------------
// 3) Fused column scan from sorted sparse events. 128 threads per bucket,
//    thread owns 8 contiguous columns: run(8t+g) = common + ofs[g].
//    Base offset computed in-block from L2-resident g_seg rows (float4,
//    independent accumulators -> high MLP). Events prefetched 8-deep.
//    grid (NSEG, CC), 128 thr.
__global__ __launch_bounds__(128) void k_B(const int* __restrict__ labels) {
    int c = blockIdx.y;
    if (labels[c] != 1) return;
    int seg = blockIdx.x, t = threadIdx.x;

    // Base: sum of segment prefixes above this segment (all L2-resident).
    float4 a0 = make_float4(0.f, 0.f, 0.f, 0.f);
    float4 a1 = make_float4(0.f, 0.f, 0.f, 0.f);
    {
        const float4* segp = reinterpret_cast<const float4*>(&g_seg[c][0][0]);
        int i0 = 2 * t, i1 = 2 * t + 1;         // float4 indices within a row
        for (int s = 0; s < seg; ++s) {
            float4 r0 = segp[s * (WW / 4) + i0]; // coalesced 128B per warp
            float4 r1 = segp[s * (WW / 4) + i1];
            a0.x += r0.x; a0.y += r0.y; a0.z += r0.z; a0.w += r0.w;
            a1.x += r1.x; a1.y += r1.y; a1.z += r1.z; a1.w += r1.w;
        }
    }
    float ofs[GCOL] = {a0.x, a0.y, a0.z, a0.w, a1.x, a1.y, a1.z, a1.w};

    float common = 0.f;
    float min_ofs = 0.f, max_ofs = 0.f;
    bool dirty = true;
    float mn = 3.4e38f, mx = -3.4e38f;
    int y = 0;

    int E = g_cnt[c][seg];
    const int2* evp = &g_evs[c][seg][0];

    int i = 0;
    while (i < E) {
        int m = min(EB, E - i);
        int2 eb[EB];
        #pragma unroll
        for (int j = 0; j < EB; ++j)
            if (j < m) eb[j] = evp[i + j];          // independent loads, MLP=EB
        #pragma unroll
        for (int j = 0; j < EB; ++j) {
            if (j >= m) break;
            int2 e = eb[j];
            int ey = e.x >> 10;
            int xe = e.x & 0x3FF;
            float se = __int_as_float(e.y);

            if (ey > y) {                            // warp-uniform gap advance
                if (dirty) {
                    float q0 = fminf(ofs[0], ofs[1]), q1 = fminf(ofs[2], ofs[3]);
                    float q2 = fminf(ofs[4], ofs[5]), q3 = fminf(ofs[6], ofs[7]);
                    min_ofs = fminf(fminf(q0, q1), fminf(q2, q3));
                    float b0 = fmaxf(ofs[0], ofs[1]), b1 = fmaxf(ofs[2], ofs[3]);
                    float b2 = fmaxf(ofs[4], ofs[5]), b3 = fmaxf(ofs[6], ofs[7]);
                    max_ofs = fmaxf(fmaxf(b0, b1), fmaxf(b2, b3));
                    dirty = false;
                }
                mn = fminf(mn, common + min_ofs);
                mx = fmaxf(mx, common + max_ofs);
                int ys = (y + 7) & ~7;               // sampled local rows (0 or 8)
                if (ys < ey) {
                    float sval = common + ofs[0];    // column 8t
                    for (; ys < ey; ys += 8)
                        g_Rm[c][seg * (SEGH / 8) + (ys >> 3)][t] = sval;
                }
                y = ey;
            }

            int owner = xe >> 3;
            if (t > owner) {
                common += se;
            } else if (t == owner) {
                int g0 = xe & 7;
                #pragma unroll
                for (int g = 0; g < GCOL; ++g)
                    if (g >= g0) ofs[g] += se;
                dirty = true;
            }
        }
        i += m;
    }

    // Flush remaining rows [y, SEGH).
    {
        if (dirty) {
            float q0 = fminf(ofs[0], ofs[1]), q1 = fminf(ofs[2], ofs[3]);
            float q2 = fminf(ofs[4], ofs[5]), q3 = fminf(ofs[6], ofs[7]);
            min_ofs = fminf(fminf(q0, q1), fminf(q2, q3));
            float b0 = fmaxf(ofs[0], ofs[1]), b1 = fmaxf(ofs[2], ofs[3]);
            float b2 = fmaxf(ofs[4], ofs[5]), b3 = fmaxf(ofs[6], ofs[7]);
            max_ofs = fmaxf(fmaxf(b0, b1), fmaxf(b2, b3));
        }
        if (y < SEGH) {
            mn = fminf(mn, common + min_ofs);
            mx = fmaxf(mx, common + max_ofs);
            int ys = (y + 7) & ~7;
            float sval = common + ofs[0];
            for (; ys < SEGH; ys += 8)
                g_Rm[c][seg * (SEGH / 8) + (ys >> 3)][t] = sval;
        }
    }

    // Block-wide min/max reduce: warp shfl + cross-warp smem.
    int lane = t & 31, warp = t >> 5;
    #pragma unroll
    for (int o = 16; o; o >>= 1) {
        mn = fminf(mn, __shfl_xor_sync(0xFFFFFFFF, mn, o));
        mx = fmaxf(mx, __shfl_xor_sync(0xFFFFFFFF, mx, o));
    }
    __shared__ float rmn[4], rmx[4];
    if (lane == 0) { rmn[warp] = mn; rmx[warp] = mx; }
    __syncthreads();
    if (t == 0) {
        float fmn = fminf(fminf(rmn[0], rmn[1]), fminf(rmn[2], rmn[3]));
        float fmx = fmaxf(fmaxf(rmx[0], rmx[1]), fmaxf(rmx[2], rmx[3]));
        atomicMinF(&g_minb[c], fmn);
        atomicMaxF(&g_maxb[c], fmx);
    }
}

// ---------------------------------------------------------------------------
// 4) Per-channel loss, normalized and atomically accumulated into out[0].
//    grid (CC), 128 thr.
__global__ void k_loss(const float* __restrict__ blob,
                       const int*   __restrict__ labels,
                       float* __restrict__ out) {
    int c = blockIdx.x, t = threadIdx.x;
    bool valid = (labels[c] == 1);
    const float* B = blob + c * hh * ww;

    float cmax = 0.f;
    for (int i = 0; i < hh; ++i) cmax = fmaxf(cmax, B[i * ww + t]);
    float rmax = 0.f;
    for (int j = 0; j < ww; ++j) rmax = fmaxf(rmax, B[t * ww + j]);
    cmax = fminf(fmaxf(cmax, EPSF), 1.f - EPSF);
    rmax = fminf(fmaxf(rmax, EPSF), 1.f - EPSF);

    float vx, vy;
    if (valid) {
        float mnv = __int_as_float(g_minb[c]);
        float mxv = __int_as_float(g_maxb[c]);
        float thr = mnv + 0.5f * (mxv - mnv + EPSF);   // normalized >= 0.5
        float scol = -3.4e38f, srow = -3.4e38f;
        for (int i = 0; i < hh; ++i) scol = fmaxf(scol, g_Rm[c][i][t]);
        for (int j = 0; j < ww; ++j) srow = fmaxf(srow, g_Rm[c][t][j]);
        vx = (scol >= thr) ? -logf(cmax) : 0.f;
        vy = (srow >= thr) ? -logf(rmax) : 0.f;
    } else {
        vx = -logf(1.f - cmax);
        vy = -logf(1.f - rmax);
    }

    __shared__ float sx[128], sy[128];
    sx[t] = vx; sy[t] = vy;
    __syncthreads();
    for (int o = 64; o; o >>= 1) {
        if (t < o) { sx[t] += sx[t + o]; sy[t] += sy[t + o]; }
        __syncthreads();
    }
    if (t == 0) {
        float vc = 0.f;
        for (int k = 0; k < CC; ++k) vc += (labels[k] == 1) ? 1.f : 0.f;
        float nvc = (float)CC - vc;
        float denom = valid ? vc : nvc;
        atomicAdd(out, sx[0] / (denom * (float)ww) + sy[0] / (denom * (float)hh));
    }
}

// ---------------------------------------------------------------------------
extern "C" void kernel_launch(void* const* d_in, const int* in_sizes, int n_in,
                              void* d_out, int out_size) {
    // metadata order: mil_result(unused), refine_result, blob_conv, rois, labels, H, W
    const float* refine = (const float*)d_in[1];
    const float* blob   = (const float*)d_in[2];
    const float* rois   = (const float*)d_in[3];
    const int*   labels = (const int*)  d_in[4];
    int R = in_sizes[3] / 5;
    float* out = (float*)d_out;

    k_zero   <<<1, 1024>>>(out);
    k_scatter<<<dim3((R + 255) / 256, CC), 256>>>(refine, rois, labels, R);
    k_A      <<<dim3(NSEG, CC), 1024>>>(labels);
    k_B      <<<dim3(NSEG, CC), 128>>>(labels);
    k_loss   <<<CC, 128>>>(blob, labels, out);
}